// round 4
// baseline (speedup 1.0000x reference)
#include <cuda_runtime.h>
#include <math_constants.h>

#define NN 100000
#define EMAX 1700000
#define SCAN_BS 1024
#define NB ((NN + SCAN_BS - 1) / SCAN_BS)   // 98

// ---------------- device scratch (static globals; no allocation) -------------
__device__ __align__(16) float g_y [NN * 64];   // (XW)*ns, gather source
__device__ __align__(16) float g_h1[NN * 64];   // layer-1 output
__device__ __align__(16) float g_h2[NN * 64];   // layer-2 output
__device__ float g_ns[NN];
__device__ float g_nd[NN];
__device__ int g_cnt_out[NN];
__device__ int g_cnt_in [NN];
__device__ int g_cursor [NN];
__device__ int g_rowptr [NN + 1];
__device__ int g_blocksum[NB];
__device__ int g_esrc[EMAX];                    // src indices sorted by dst
__device__ int g_is64;

// ---------------- packed f32x2 helpers ---------------------------------------
__device__ __forceinline__ void ffma2(unsigned long long& d,
                                      unsigned long long a,
                                      unsigned long long b) {
    asm("fma.rn.f32x2 %0, %1, %2, %0;" : "+l"(d) : "l"(a), "l"(b));
}
__device__ __forceinline__ unsigned long long packdup(float x) {
    unsigned long long u;
    asm("mov.b64 %0, {%1, %1};" : "=l"(u) : "f"(x));
    return u;
}
__device__ __forceinline__ float2 unpack2(unsigned long long u) {
    float2 r;
    asm("mov.b64 {%0, %1}, %2;" : "=f"(r.x), "=f"(r.y) : "l"(u));
    return r;
}
__device__ __forceinline__ unsigned long long pack2(float a, float b) {
    unsigned long long u;
    asm("mov.b64 %0, {%1, %2};" : "=l"(u) : "f"(a), "f"(b));
    return u;
}

__device__ __forceinline__ int load_idx(const void* p, int i, int is64) {
    return is64 ? (int)((const long long*)p)[i] : ((const int*)p)[i];
}

// ---------------- zero histograms + index-width detection ---------------------
__global__ void zero_detect_kernel(const void* src, int E) {
    int i = blockIdx.x * blockDim.x + threadIdx.x;
    if (i < NN) { g_cnt_out[i] = 0; g_cnt_in[i] = 0; }
    if (blockIdx.x == 0 && threadIdx.x == 0) {
        const long long* p = (const long long*)src;
        int n = E < 8 ? E : 8;
        int ok = 1;
        for (int j = 0; j < n; j++) {
            long long v = p[j];
            if (v < 0 || v >= (long long)NN) { ok = 0; break; }
        }
        g_is64 = ok;
    }
}

// ---------------- degree histograms (int atomics) -----------------------------
__global__ void hist_kernel(const void* __restrict__ src,
                            const void* __restrict__ dst, int E) {
    int e = blockIdx.x * blockDim.x + threadIdx.x;
    if (e >= E) return;
    int is64 = g_is64;
    atomicAdd(&g_cnt_out[load_idx(src, e, is64)], 1);
    atomicAdd(&g_cnt_in [load_idx(dst, e, is64)], 1);
}

// ---------------- exclusive scan of cnt_in -> rowptr --------------------------
__global__ void __launch_bounds__(SCAN_BS) scan1_kernel() {
    __shared__ int sh[SCAN_BS];
    int tid = threadIdx.x;
    int i = blockIdx.x * SCAN_BS + tid;
    int v = (i < NN) ? g_cnt_in[i] : 0;
    sh[tid] = v;
    __syncthreads();
    #pragma unroll
    for (int off = 1; off < SCAN_BS; off <<= 1) {
        int t = (tid >= off) ? sh[tid - off] : 0;
        __syncthreads();
        sh[tid] += t;
        __syncthreads();
    }
    if (i < NN) g_rowptr[i] = sh[tid] - v;          // exclusive (per-block)
    if (tid == SCAN_BS - 1) g_blocksum[blockIdx.x] = sh[tid];
}

// warp-parallel scan of the 98 block sums
__global__ void scan2_kernel() {
    int lane = threadIdx.x;
    int carry = 0;
    const int CH = (NB + 31) / 32;
    for (int c = 0; c < CH; c++) {
        int i = c * 32 + lane;
        int v0 = (i < NB) ? g_blocksum[i] : 0;
        int v = v0;
        #pragma unroll
        for (int off = 1; off < 32; off <<= 1) {
            int t = __shfl_up_sync(0xffffffffu, v, off);
            if (lane >= off) v += t;
        }
        if (i < NB) g_blocksum[i] = carry + v - v0;  // exclusive
        carry += __shfl_sync(0xffffffffu, v, 31);
    }
    if (lane == 0) g_rowptr[NN] = carry;             // == E
}

__global__ void __launch_bounds__(SCAN_BS) scan3_kernel() {
    int i = blockIdx.x * SCAN_BS + threadIdx.x;
    if (i >= NN) return;
    g_rowptr[i] += g_blocksum[blockIdx.x];
    g_cursor[i] = 0;
    int o = g_cnt_out[i], d = g_cnt_in[i];
    g_ns[i] = (o > 0) ? rsqrtf((float)o) : 0.f;
    g_nd[i] = (d > 0) ? rsqrtf((float)d) : 0.f;
}

// ---------------- edge placement: CSR by dst ----------------------------------
__global__ void place_kernel(const void* __restrict__ src,
                             const void* __restrict__ dst, int E) {
    int e = blockIdx.x * blockDim.x + threadIdx.x;
    if (e >= E) return;
    int is64 = g_is64;
    int s = load_idx(src, e, is64);
    int d = load_idx(dst, e, is64);
    int pos = g_rowptr[d] + atomicAdd(&g_cursor[d], 1);
    g_esrc[pos] = s;
}

// ---------------- GEMM (FFMA2): Y = (X @ W) * ns ------------------------------
// 256 threads, 256 rows/block. lane = local row; per k: broadcast W row via
// LDS.128 (2 packed col-pairs each), Xt[k][r] conflict-free, 32 FFMA2/k/warp.
#define XT_STRIDE 257
template<int IN, int OUT>
__global__ void __launch_bounds__(256) gemm2_kernel(
        const float* __restrict__ X, const float* __restrict__ W,
        float* __restrict__ Y) {
    extern __shared__ float sh[];
    float* Ws = sh;                    // IN * OUT
    float* Xt = sh + IN * OUT;         // IN rows of stride XT_STRIDE

    int tid = threadIdx.x;
    for (int i = tid * 4; i < IN * OUT; i += 256 * 4)
        *(float4*)&Ws[i] = *(const float4*)&W[i];

    int row0 = blockIdx.x * 256;
    constexpr int IN4 = IN / 4;
    for (int i = tid; i < 256 * IN4; i += 256) {
        int r = i / IN4, k4 = i % IN4;
        int gr = row0 + r;
        float4 v = (gr < NN) ? __ldg((const float4*)&X[(size_t)gr * IN + k4 * 4])
                             : make_float4(0.f, 0.f, 0.f, 0.f);
        Xt[(4 * k4 + 0) * XT_STRIDE + r] = v.x;
        Xt[(4 * k4 + 1) * XT_STRIDE + r] = v.y;
        Xt[(4 * k4 + 2) * XT_STRIDE + r] = v.z;
        Xt[(4 * k4 + 3) * XT_STRIDE + r] = v.w;
    }
    __syncthreads();

    int r = tid;                        // local row 0..255
    int gr = row0 + r;
    constexpr int NC = OUT / 2;
    unsigned long long acc[NC];
    #pragma unroll
    for (int c = 0; c < NC; c++) acc[c] = 0ull;

    #pragma unroll 2
    for (int k = 0; k < IN; k++) {
        unsigned long long xd = packdup(Xt[k * XT_STRIDE + r]);
        const float4* wrow = (const float4*)&Ws[k * OUT];
        #pragma unroll
        for (int c4 = 0; c4 < OUT / 4; c4++) {
            float4 wv = wrow[c4];                   // LDS.128 broadcast
            ffma2(acc[2 * c4 + 0], xd, pack2(wv.x, wv.y));
            ffma2(acc[2 * c4 + 1], xd, pack2(wv.z, wv.w));
        }
    }

    if (gr < NN) {
        float s = g_ns[gr];
        #pragma unroll
        for (int c2 = 0; c2 < NC; c2++) {
            float2 v = unpack2(acc[c2]);
            *(float2*)&Y[(size_t)gr * OUT + 2 * c2] =
                make_float2(v.x * s, v.y * s);
        }
    }
}

// ---------------- fused SpMM-gather + epilogue --------------------------------
// One warp per dst row; lane covers 4 cols (float4 gathers), 8 edges in flight.
template<int OUT, bool RELU>
__global__ void __launch_bounds__(256) spmm_epi_kernel(
        const float* __restrict__ Y, const float* __restrict__ bias,
        float* __restrict__ Out) {
    int row = blockIdx.x * 8 + (threadIdx.x >> 5);
    if (row >= NN) return;
    int lane = threadIdx.x & 31;
    int c0 = 4 * lane;
    bool valid = c0 < OUT;

    int beg = g_rowptr[row], end = g_rowptr[row + 1];
    float4 aA = make_float4(0.f, 0.f, 0.f, 0.f);
    float4 aB = make_float4(0.f, 0.f, 0.f, 0.f);

    for (int base = beg; base < end; base += 32) {
        int rem = end - base; if (rem > 32) rem = 32;
        int my = (lane < rem) ? g_esrc[base + lane] : 0;
        int j = 0;
        for (; j + 8 <= rem; j += 8) {
            int s[8];
            #pragma unroll
            for (int u = 0; u < 8; u++)
                s[u] = __shfl_sync(0xffffffffu, my, j + u);
            if (valid) {
                float4 v[8];
                #pragma unroll
                for (int u = 0; u < 8; u++)
                    v[u] = __ldg((const float4*)&Y[(size_t)s[u] * OUT + c0]);
                #pragma unroll
                for (int u = 0; u < 8; u += 2) {
                    aA.x += v[u].x; aA.y += v[u].y; aA.z += v[u].z; aA.w += v[u].w;
                    aB.x += v[u+1].x; aB.y += v[u+1].y; aB.z += v[u+1].z; aB.w += v[u+1].w;
                }
            }
        }
        for (; j < rem; j++) {
            int s = __shfl_sync(0xffffffffu, my, j);
            if (valid) {
                float4 v = __ldg((const float4*)&Y[(size_t)s * OUT + c0]);
                aA.x += v.x; aA.y += v.y; aA.z += v.z; aA.w += v.w;
            }
        }
    }
    aA.x += aB.x; aA.y += aB.y; aA.z += aB.z; aA.w += aB.w;

    float ndv = g_nd[row];
    float v0 = -CUDART_INF_F, v1 = -CUDART_INF_F,
          v2 = -CUDART_INF_F, v3 = -CUDART_INF_F;
    if (valid) {
        float4 b = __ldg((const float4*)&bias[c0]);
        v0 = aA.x * ndv + b.x; v1 = aA.y * ndv + b.y;
        v2 = aA.z * ndv + b.z; v3 = aA.w * ndv + b.w;
        if (RELU) {
            v0 = fmaxf(v0, 0.f); v1 = fmaxf(v1, 0.f);
            v2 = fmaxf(v2, 0.f); v3 = fmaxf(v3, 0.f);
        }
    }
    // reduce within 16-lane groups (offsets 8,4,2,1 keep groups closed)
    float m = fmaxf(fmaxf(v0, v1), fmaxf(v2, v3));
    #pragma unroll
    for (int o = 8; o; o >>= 1) m = fmaxf(m, __shfl_xor_sync(0xffffffffu, m, o));
    float s = valid ? (__expf(v0 - m) + __expf(v1 - m) +
                       __expf(v2 - m) + __expf(v3 - m)) : 0.f;
    #pragma unroll
    for (int o = 8; o; o >>= 1) s += __shfl_xor_sync(0xffffffffu, s, o);
    float ls = logf(s) + m;
    if (valid)
        *(float4*)&Out[(size_t)row * OUT + c0] =
            make_float4(v0 - ls, v1 - ls, v2 - ls, v3 - ls);
}

// ---------------- launcher ----------------------------------------------------
extern "C" void kernel_launch(void* const* d_in, const int* in_sizes, int n_in,
                              void* d_out, int out_size) {
    const float* feats = (const float*)d_in[0];
    const void*  src   = d_in[1];
    const void*  dst   = d_in[2];
    const float* W0    = (const float*)d_in[3];
    const float* b0    = (const float*)d_in[4];
    const float* W1    = (const float*)d_in[5];
    const float* b1    = (const float*)d_in[6];
    const float* W2    = (const float*)d_in[7];
    const float* b2    = (const float*)d_in[8];
    float* out = (float*)d_out;
    int E = in_sizes[1];

    float *p_y = nullptr, *p_h1 = nullptr, *p_h2 = nullptr;
    cudaGetSymbolAddress((void**)&p_y,  g_y);
    cudaGetSymbolAddress((void**)&p_h1, g_h1);
    cudaGetSymbolAddress((void**)&p_h2, g_h2);

    const int GB = (NN + 255) / 256;  // gemm blocks (256 rows each)
    const int SB = (NN + 7) / 8;      // spmm blocks (warp per row)
    const int EB = (E + 255) / 256;   // per-edge blocks

    // dynamic smem sizes per layer
    const int sm0 = (128 * 64 + 128 * XT_STRIDE) * 4;
    const int sm1 = (64 * 64 + 64 * XT_STRIDE) * 4;
    const int sm2 = (64 * 40 + 64 * XT_STRIDE) * 4;
    cudaFuncSetAttribute(gemm2_kernel<128, 64>,
                         cudaFuncAttributeMaxDynamicSharedMemorySize, sm0);
    cudaFuncSetAttribute(gemm2_kernel<64, 64>,
                         cudaFuncAttributeMaxDynamicSharedMemorySize, sm1);
    cudaFuncSetAttribute(gemm2_kernel<64, 40>,
                         cudaFuncAttributeMaxDynamicSharedMemorySize, sm2);

    // ---- CSR build
    zero_detect_kernel<<<GB * 2, 256>>>(src, E);
    hist_kernel<<<EB, 256>>>(src, dst, E);
    scan1_kernel<<<NB, SCAN_BS>>>();
    scan2_kernel<<<1, 32>>>();
    scan3_kernel<<<NB, SCAN_BS>>>();
    place_kernel<<<EB, 256>>>(src, dst, E);

    // ---- layer 0: 128 -> 64, relu + log_softmax -> g_h1
    gemm2_kernel<128, 64><<<GB, 256, sm0>>>(feats, W0, p_y);
    spmm_epi_kernel<64, true><<<SB, 256>>>(p_y, b0, p_h1);

    // ---- layer 1: 64 -> 64, relu + log_softmax -> g_h2
    gemm2_kernel<64, 64><<<GB, 256, sm1>>>(p_h1, W1, p_y);
    spmm_epi_kernel<64, true><<<SB, 256>>>(p_y, b1, p_h2);

    // ---- layer 2: 64 -> 40, log_softmax -> d_out
    gemm2_kernel<64, 40><<<GB, 256, sm2>>>(p_h2, W2, p_y);
    spmm_epi_kernel<40, false><<<SB, 256>>>(p_y, b2, out);
}

// round 5
// speedup vs baseline: 1.1926x; 1.1926x over previous
#include <cuda_runtime.h>
#include <math_constants.h>

#define NN 100000
#define EMAX 1700000
#define SCAN_BS 1024
#define NB ((NN + SCAN_BS - 1) / SCAN_BS)   // 98

// ---------------- device scratch (static globals; no allocation) -------------
__device__ __align__(16) float g_y [NN * 64];   // (XW)*ns, gather source
__device__ __align__(16) float g_h1[NN * 64];   // layer-1 output
__device__ __align__(16) float g_h2[NN * 64];   // layer-2 output
__device__ float g_ns[NN];
__device__ float g_nd[NN];
__device__ int g_cnt_out[NN];
__device__ int g_cnt_in [NN];
__device__ int g_cursor [NN];
__device__ int g_rowptr [NN + 1];
__device__ int g_blocksum[NB];
__device__ int g_esrc[EMAX];                    // src indices sorted by dst
__device__ int g_is64;

// ---------------- packed f32x2 helpers ---------------------------------------
__device__ __forceinline__ void ffma2(unsigned long long& d,
                                      unsigned long long a,
                                      unsigned long long b) {
    asm("fma.rn.f32x2 %0, %1, %2, %0;" : "+l"(d) : "l"(a), "l"(b));
}
__device__ __forceinline__ unsigned long long packdup(float x) {
    unsigned long long u;
    asm("mov.b64 %0, {%1, %1};" : "=l"(u) : "f"(x));
    return u;
}
__device__ __forceinline__ float2 unpack2(unsigned long long u) {
    float2 r;
    asm("mov.b64 {%0, %1}, %2;" : "=f"(r.x), "=f"(r.y) : "l"(u));
    return r;
}
__device__ __forceinline__ unsigned long long pack2(float a, float b) {
    unsigned long long u;
    asm("mov.b64 %0, {%1, %2};" : "=l"(u) : "f"(a), "f"(b));
    return u;
}

__device__ __forceinline__ int load_idx(const void* p, int i, int is64) {
    return is64 ? (int)((const long long*)p)[i] : ((const int*)p)[i];
}

// ---------------- zero histograms + index-width detection ---------------------
__global__ void zero_detect_kernel(const void* src, int E) {
    int i = blockIdx.x * blockDim.x + threadIdx.x;
    if (i < NN) { g_cnt_out[i] = 0; g_cnt_in[i] = 0; }
    if (blockIdx.x == 0 && threadIdx.x == 0) {
        const long long* p = (const long long*)src;
        int n = E < 8 ? E : 8;
        int ok = 1;
        for (int j = 0; j < n; j++) {
            long long v = p[j];
            if (v < 0 || v >= (long long)NN) { ok = 0; break; }
        }
        g_is64 = ok;
    }
}

// ---------------- degree histograms (int atomics) -----------------------------
__global__ void hist_kernel(const void* __restrict__ src,
                            const void* __restrict__ dst, int E) {
    int e = blockIdx.x * blockDim.x + threadIdx.x;
    if (e >= E) return;
    int is64 = g_is64;
    atomicAdd(&g_cnt_out[load_idx(src, e, is64)], 1);
    atomicAdd(&g_cnt_in [load_idx(dst, e, is64)], 1);
}

// ---------------- exclusive scan of cnt_in -> rowptr --------------------------
__global__ void __launch_bounds__(SCAN_BS) scan1_kernel() {
    __shared__ int sh[SCAN_BS];
    int tid = threadIdx.x;
    int i = blockIdx.x * SCAN_BS + tid;
    int v = (i < NN) ? g_cnt_in[i] : 0;
    sh[tid] = v;
    __syncthreads();
    #pragma unroll
    for (int off = 1; off < SCAN_BS; off <<= 1) {
        int t = (tid >= off) ? sh[tid - off] : 0;
        __syncthreads();
        sh[tid] += t;
        __syncthreads();
    }
    if (i < NN) g_rowptr[i] = sh[tid] - v;          // exclusive (per-block)
    if (tid == SCAN_BS - 1) g_blocksum[blockIdx.x] = sh[tid];
}

// warp-parallel scan of the 98 block sums
__global__ void scan2_kernel() {
    int lane = threadIdx.x;
    int carry = 0;
    const int CH = (NB + 31) / 32;
    for (int c = 0; c < CH; c++) {
        int i = c * 32 + lane;
        int v0 = (i < NB) ? g_blocksum[i] : 0;
        int v = v0;
        #pragma unroll
        for (int off = 1; off < 32; off <<= 1) {
            int t = __shfl_up_sync(0xffffffffu, v, off);
            if (lane >= off) v += t;
        }
        if (i < NB) g_blocksum[i] = carry + v - v0;  // exclusive
        carry += __shfl_sync(0xffffffffu, v, 31);
    }
    if (lane == 0) g_rowptr[NN] = carry;             // == E
}

__global__ void __launch_bounds__(SCAN_BS) scan3_kernel() {
    int i = blockIdx.x * SCAN_BS + threadIdx.x;
    if (i >= NN) return;
    g_rowptr[i] += g_blocksum[blockIdx.x];
    g_cursor[i] = 0;
    int o = g_cnt_out[i], d = g_cnt_in[i];
    g_ns[i] = (o > 0) ? rsqrtf((float)o) : 0.f;
    g_nd[i] = (d > 0) ? rsqrtf((float)d) : 0.f;
}

// ---------------- edge placement: CSR by dst ----------------------------------
__global__ void place_kernel(const void* __restrict__ src,
                             const void* __restrict__ dst, int E) {
    int e = blockIdx.x * blockDim.x + threadIdx.x;
    if (e >= E) return;
    int is64 = g_is64;
    int s = load_idx(src, e, is64);
    int d = load_idx(dst, e, is64);
    int pos = g_rowptr[d] + atomicAdd(&g_cursor[d], 1);
    g_esrc[pos] = s;
}

// ---------------- GEMM: Y[n,OUT] = (X[n,IN] @ W[IN,OUT]) * ns[n] -------------
// Round-2 skeleton (32 rows/block, 256 thr, 4 CTAs/SM) with FFMA2 inner loop:
// per k4-group per thread: 4 LDS.128 (Xs) + 4 LDS.64 (W pairs) + 16 FFMA2.
template<int IN, int OUT>
__global__ void __launch_bounds__(256) gemm_scale_kernel(
        const float* __restrict__ X, const float* __restrict__ W,
        float* __restrict__ Y) {
    __shared__ float Ws[IN * OUT];
    __shared__ float Xs[32][IN];

    int tid = threadIdx.x;
    for (int i = tid * 4; i < IN * OUT; i += 256 * 4)
        *(float4*)&Ws[i] = *(const float4*)&W[i];

    int row0 = blockIdx.x * 32;
    constexpr int IN4 = IN / 4;
    for (int i = tid; i < 32 * IN4; i += 256) {
        int r = i / IN4, c = i % IN4;
        int gr = row0 + r;
        float4 v = (gr < NN) ? __ldg((const float4*)&X[(size_t)gr * IN + c * 4])
                             : make_float4(0.f, 0.f, 0.f, 0.f);
        *(float4*)&Xs[r][c * 4] = v;
    }
    __syncthreads();

    int lane = tid & 31, rg = tid >> 5;
    int c0 = 2 * lane;
    if (c0 >= OUT) return;

    unsigned long long acc[4];
    #pragma unroll
    for (int r = 0; r < 4; r++) acc[r] = 0ull;

    #pragma unroll
    for (int k4 = 0; k4 < IN4; k4++) {
        float4 xv[4];
        #pragma unroll
        for (int r = 0; r < 4; r++)
            xv[r] = *(float4*)&Xs[rg * 4 + r][k4 * 4];
        #pragma unroll
        for (int kk = 0; kk < 4; kk++) {
            float2 w = *(float2*)&Ws[(k4 * 4 + kk) * OUT + c0];
            unsigned long long wp = pack2(w.x, w.y);
            float xk0 = (kk == 0) ? xv[0].x : (kk == 1) ? xv[0].y
                      : (kk == 2) ? xv[0].z : xv[0].w;
            float xk1 = (kk == 0) ? xv[1].x : (kk == 1) ? xv[1].y
                      : (kk == 2) ? xv[1].z : xv[1].w;
            float xk2 = (kk == 0) ? xv[2].x : (kk == 1) ? xv[2].y
                      : (kk == 2) ? xv[2].z : xv[2].w;
            float xk3 = (kk == 0) ? xv[3].x : (kk == 1) ? xv[3].y
                      : (kk == 2) ? xv[3].z : xv[3].w;
            ffma2(acc[0], packdup(xk0), wp);
            ffma2(acc[1], packdup(xk1), wp);
            ffma2(acc[2], packdup(xk2), wp);
            ffma2(acc[3], packdup(xk3), wp);
        }
    }
    #pragma unroll
    for (int r = 0; r < 4; r++) {
        int gr = row0 + rg * 4 + r;
        if (gr < NN) {
            float s = g_ns[gr];
            float2 v = unpack2(acc[r]);
            *(float2*)&Y[(size_t)gr * OUT + c0] =
                make_float2(v.x * s, v.y * s);
        }
    }
}

// ---------------- fused SpMM-gather + epilogue --------------------------------
// One warp per dst row; lane covers 4 cols (float4 gathers), 8 edges in flight.
template<int OUT, bool RELU>
__global__ void __launch_bounds__(256) spmm_epi_kernel(
        const float* __restrict__ Y, const float* __restrict__ bias,
        float* __restrict__ Out) {
    int row = blockIdx.x * 8 + (threadIdx.x >> 5);
    if (row >= NN) return;
    int lane = threadIdx.x & 31;
    int c0 = 4 * lane;
    bool valid = c0 < OUT;

    int beg = g_rowptr[row], end = g_rowptr[row + 1];
    float4 aA = make_float4(0.f, 0.f, 0.f, 0.f);
    float4 aB = make_float4(0.f, 0.f, 0.f, 0.f);

    for (int base = beg; base < end; base += 32) {
        int rem = end - base; if (rem > 32) rem = 32;
        int my = (lane < rem) ? g_esrc[base + lane] : 0;
        int j = 0;
        for (; j + 8 <= rem; j += 8) {
            int s[8];
            #pragma unroll
            for (int u = 0; u < 8; u++)
                s[u] = __shfl_sync(0xffffffffu, my, j + u);
            if (valid) {
                float4 v[8];
                #pragma unroll
                for (int u = 0; u < 8; u++)
                    v[u] = __ldg((const float4*)&Y[(size_t)s[u] * OUT + c0]);
                #pragma unroll
                for (int u = 0; u < 8; u += 2) {
                    aA.x += v[u].x; aA.y += v[u].y; aA.z += v[u].z; aA.w += v[u].w;
                    aB.x += v[u+1].x; aB.y += v[u+1].y; aB.z += v[u+1].z; aB.w += v[u+1].w;
                }
            }
        }
        for (; j < rem; j++) {
            int s = __shfl_sync(0xffffffffu, my, j);
            if (valid) {
                float4 v = __ldg((const float4*)&Y[(size_t)s * OUT + c0]);
                aA.x += v.x; aA.y += v.y; aA.z += v.z; aA.w += v.w;
            }
        }
    }
    aA.x += aB.x; aA.y += aB.y; aA.z += aB.z; aA.w += aB.w;

    float ndv = g_nd[row];
    float v0 = -CUDART_INF_F, v1 = -CUDART_INF_F,
          v2 = -CUDART_INF_F, v3 = -CUDART_INF_F;
    if (valid) {
        float4 b = __ldg((const float4*)&bias[c0]);
        v0 = aA.x * ndv + b.x; v1 = aA.y * ndv + b.y;
        v2 = aA.z * ndv + b.z; v3 = aA.w * ndv + b.w;
        if (RELU) {
            v0 = fmaxf(v0, 0.f); v1 = fmaxf(v1, 0.f);
            v2 = fmaxf(v2, 0.f); v3 = fmaxf(v3, 0.f);
        }
    }
    // reduce within 16-lane groups (offsets 8,4,2,1 keep groups closed)
    float m = fmaxf(fmaxf(v0, v1), fmaxf(v2, v3));
    #pragma unroll
    for (int o = 8; o; o >>= 1) m = fmaxf(m, __shfl_xor_sync(0xffffffffu, m, o));
    float s = valid ? (__expf(v0 - m) + __expf(v1 - m) +
                       __expf(v2 - m) + __expf(v3 - m)) : 0.f;
    #pragma unroll
    for (int o = 8; o; o >>= 1) s += __shfl_xor_sync(0xffffffffu, s, o);
    float ls = logf(s) + m;
    if (valid)
        *(float4*)&Out[(size_t)row * OUT + c0] =
            make_float4(v0 - ls, v1 - ls, v2 - ls, v3 - ls);
}

// ---------------- launcher ----------------------------------------------------
extern "C" void kernel_launch(void* const* d_in, const int* in_sizes, int n_in,
                              void* d_out, int out_size) {
    const float* feats = (const float*)d_in[0];
    const void*  src   = d_in[1];
    const void*  dst   = d_in[2];
    const float* W0    = (const float*)d_in[3];
    const float* b0    = (const float*)d_in[4];
    const float* W1    = (const float*)d_in[5];
    const float* b1    = (const float*)d_in[6];
    const float* W2    = (const float*)d_in[7];
    const float* b2    = (const float*)d_in[8];
    float* out = (float*)d_out;
    int E = in_sizes[1];

    float *p_y = nullptr, *p_h1 = nullptr, *p_h2 = nullptr;
    cudaGetSymbolAddress((void**)&p_y,  g_y);
    cudaGetSymbolAddress((void**)&p_h1, g_h1);
    cudaGetSymbolAddress((void**)&p_h2, g_h2);

    const int GB = (NN + 31) / 32;    // gemm blocks (32 rows each)
    const int SB = (NN + 7) / 8;      // spmm blocks (warp per row)
    const int EB = (E + 255) / 256;   // per-edge blocks
    const int ZB = (NN + 255) / 256;  // zero blocks

    // ---- CSR build (int atomics only)
    zero_detect_kernel<<<ZB, 256>>>(src, E);
    hist_kernel<<<EB, 256>>>(src, dst, E);
    scan1_kernel<<<NB, SCAN_BS>>>();
    scan2_kernel<<<1, 32>>>();
    scan3_kernel<<<NB, SCAN_BS>>>();
    place_kernel<<<EB, 256>>>(src, dst, E);

    // ---- layer 0: 128 -> 64, relu + log_softmax -> g_h1
    gemm_scale_kernel<128, 64><<<GB, 256>>>(feats, W0, p_y);
    spmm_epi_kernel<64, true><<<SB, 256>>>(p_y, b0, p_h1);

    // ---- layer 1: 64 -> 64, relu + log_softmax -> g_h2
    gemm_scale_kernel<64, 64><<<GB, 256>>>(p_h1, W1, p_y);
    spmm_epi_kernel<64, true><<<SB, 256>>>(p_y, b1, p_h2);

    // ---- layer 2: 64 -> 40, log_softmax -> d_out
    gemm_scale_kernel<64, 40><<<GB, 256>>>(p_h2, W2, p_y);
    spmm_epi_kernel<40, false><<<SB, 256>>>(p_y, b2, out);
}

// round 6
// speedup vs baseline: 1.4244x; 1.1944x over previous
#include <cuda_runtime.h>
#include <math_constants.h>

#define NN 100000
#define EMAX 1700000
#define SCAN_BS 1024
#define NB ((NN + SCAN_BS - 1) / SCAN_BS)   // 98

// ---------------- device scratch (static globals; no allocation) -------------
__device__ __align__(16) float g_y [NN * 64];   // (XW)*ns, gather source
__device__ __align__(16) float g_h1[NN * 64];   // layer-1 output
__device__ __align__(16) float g_h2[NN * 64];   // layer-2 output
__device__ float g_ns[NN];
__device__ float g_nd[NN];
__device__ int g_cnt_out[NN];
__device__ int g_cnt_in [NN];
__device__ int g_cursor [NN];
__device__ int g_rowptr [NN + 1];
__device__ int g_blocksum[NB];
__device__ int g_esrc[EMAX];                    // src indices sorted by dst
__device__ int g_is64;

__device__ __forceinline__ int load_idx(const void* p, int i, int is64) {
    return is64 ? (int)((const long long*)p)[i] : ((const int*)p)[i];
}

// ---------------- zero histograms + index-width detection ---------------------
__global__ void zero_detect_kernel(const void* src, int E) {
    int i = blockIdx.x * blockDim.x + threadIdx.x;
    if (i < NN) { g_cnt_out[i] = 0; g_cnt_in[i] = 0; }
    if (blockIdx.x == 0 && threadIdx.x == 0) {
        const long long* p = (const long long*)src;
        int n = E < 8 ? E : 8;
        int ok = 1;
        for (int j = 0; j < n; j++) {
            long long v = p[j];
            if (v < 0 || v >= (long long)NN) { ok = 0; break; }
        }
        g_is64 = ok;
    }
}

// ---------------- shared GEMM body (round-2 proven version) -------------------
// 32 rows/block, 256 thr: lane covers 2 cols, 8 row-groups x 4 rows.
template<int IN, int OUT, bool SCALE>
__device__ __forceinline__ void gemm_body(
        const float* __restrict__ X, const float* __restrict__ W,
        float* __restrict__ Y, int row0, float* Ws, float* Xs) {
    int tid = threadIdx.x;
    for (int i = tid * 4; i < IN * OUT; i += 256 * 4)
        *(float4*)&Ws[i] = *(const float4*)&W[i];

    constexpr int IN4 = IN / 4;
    for (int i = tid; i < 32 * IN4; i += 256) {
        int r = i / IN4, c = i % IN4;
        int gr = row0 + r;
        float4 v = (gr < NN) ? __ldg((const float4*)&X[(size_t)gr * IN + c * 4])
                             : make_float4(0.f, 0.f, 0.f, 0.f);
        *(float4*)&Xs[r * IN + c * 4] = v;
    }
    __syncthreads();

    int lane = tid & 31, rg = tid >> 5;
    int c0 = 2 * lane;
    if (c0 >= OUT) return;

    float acc[4][2] = {};
    #pragma unroll
    for (int k4 = 0; k4 < IN4; k4++) {
        float xv[4][4];
        #pragma unroll
        for (int r = 0; r < 4; r++) {
            float4 t = *(float4*)&Xs[(rg * 4 + r) * IN + k4 * 4];
            xv[r][0] = t.x; xv[r][1] = t.y; xv[r][2] = t.z; xv[r][3] = t.w;
        }
        #pragma unroll
        for (int kk = 0; kk < 4; kk++) {
            float2 w = *(float2*)&Ws[(k4 * 4 + kk) * OUT + c0];
            #pragma unroll
            for (int r = 0; r < 4; r++) {
                acc[r][0] += xv[r][kk] * w.x;
                acc[r][1] += xv[r][kk] * w.y;
            }
        }
    }
    #pragma unroll
    for (int r = 0; r < 4; r++) {
        int gr = row0 + rg * 4 + r;
        if (gr < NN) {
            float s = SCALE ? g_ns[gr] : 1.f;
            *(float2*)&Y[(size_t)gr * OUT + c0] =
                make_float2(acc[r][0] * s, acc[r][1] * s);
        }
    }
}

// ---------------- fused launch: edge histogram || layer-0 GEMM (unscaled) ----
// Blocks [0,EB): histogram (LTS atomics). Blocks [EB,EB+GB): GEMM0 (FFMA).
// Complementary pipes co-run inside one launch; no streams needed.
__global__ void __launch_bounds__(256) histgemm_kernel(
        const void* __restrict__ src, const void* __restrict__ dst, int E,
        int EB, const float* __restrict__ X, const float* __restrict__ W,
        float* __restrict__ Y) {
    __shared__ float Ws[128 * 64];
    __shared__ float Xs[32 * 128];
    if ((int)blockIdx.x < EB) {
        int e = blockIdx.x * 256 + threadIdx.x;
        if (e >= E) return;
        int is64 = g_is64;
        atomicAdd(&g_cnt_out[load_idx(src, e, is64)], 1);
        atomicAdd(&g_cnt_in [load_idx(dst, e, is64)], 1);
        return;
    }
    gemm_body<128, 64, false>(X, W, Y, (blockIdx.x - EB) * 32, Ws, Xs);
}

// ---------------- standalone scaled GEMM (layers 1, 2) ------------------------
template<int IN, int OUT>
__global__ void __launch_bounds__(256) gemm_scale_kernel(
        const float* __restrict__ X, const float* __restrict__ W,
        float* __restrict__ Y) {
    __shared__ float Ws[IN * OUT];
    __shared__ float Xs[32 * IN];
    gemm_body<IN, OUT, true>(X, W, Y, blockIdx.x * 32, Ws, Xs);
}

// ---------------- exclusive scan of cnt_in -> rowptr --------------------------
__global__ void __launch_bounds__(SCAN_BS) scan1_kernel() {
    __shared__ int sh[SCAN_BS];
    int tid = threadIdx.x;
    int i = blockIdx.x * SCAN_BS + tid;
    int v = (i < NN) ? g_cnt_in[i] : 0;
    sh[tid] = v;
    __syncthreads();
    #pragma unroll
    for (int off = 1; off < SCAN_BS; off <<= 1) {
        int t = (tid >= off) ? sh[tid - off] : 0;
        __syncthreads();
        sh[tid] += t;
        __syncthreads();
    }
    if (i < NN) g_rowptr[i] = sh[tid] - v;          // exclusive (per-block)
    if (tid == SCAN_BS - 1) g_blocksum[blockIdx.x] = sh[tid];
}

// warp-parallel scan of the 98 block sums
__global__ void scan2_kernel() {
    int lane = threadIdx.x;
    int carry = 0;
    const int CH = (NB + 31) / 32;
    for (int c = 0; c < CH; c++) {
        int i = c * 32 + lane;
        int v0 = (i < NB) ? g_blocksum[i] : 0;
        int v = v0;
        #pragma unroll
        for (int off = 1; off < 32; off <<= 1) {
            int t = __shfl_up_sync(0xffffffffu, v, off);
            if (lane >= off) v += t;
        }
        if (i < NB) g_blocksum[i] = carry + v - v0;  // exclusive
        carry += __shfl_sync(0xffffffffu, v, 31);
    }
    if (lane == 0) g_rowptr[NN] = carry;             // == E
}

// scan3: finalize rowptr, norms, cursors, AND scale Y0 by ns (GEMM0 was unscaled)
__global__ void __launch_bounds__(SCAN_BS) scan3_kernel(float* __restrict__ Y) {
    int i = blockIdx.x * SCAN_BS + threadIdx.x;
    if (i >= NN) return;
    g_rowptr[i] += g_blocksum[blockIdx.x];
    g_cursor[i] = 0;
    int o = g_cnt_out[i], d = g_cnt_in[i];
    float nsv = (o > 0) ? rsqrtf((float)o) : 0.f;
    g_ns[i] = nsv;
    g_nd[i] = (d > 0) ? rsqrtf((float)d) : 0.f;
    float4* yr = (float4*)&Y[(size_t)i * 64];
    #pragma unroll
    for (int j = 0; j < 16; j++) {
        float4 v = yr[j];
        v.x *= nsv; v.y *= nsv; v.z *= nsv; v.w *= nsv;
        yr[j] = v;
    }
}

// ---------------- edge placement: CSR by dst ----------------------------------
__global__ void place_kernel(const void* __restrict__ src,
                             const void* __restrict__ dst, int E) {
    int e = blockIdx.x * blockDim.x + threadIdx.x;
    if (e >= E) return;
    int is64 = g_is64;
    int s = load_idx(src, e, is64);
    int d = load_idx(dst, e, is64);
    int pos = g_rowptr[d] + atomicAdd(&g_cursor[d], 1);
    g_esrc[pos] = s;
}

// ---------------- fused SpMM-gather + epilogue (round-2 proven version) -------
template<int OUT, bool RELU>
__global__ void __launch_bounds__(256) spmm_epi_kernel(
        const float* __restrict__ Y, const float* __restrict__ bias,
        float* __restrict__ Out) {
    int row = blockIdx.x * 8 + (threadIdx.x >> 5);
    if (row >= NN) return;
    int lane = threadIdx.x & 31;
    int c0 = 2 * lane;
    bool valid = c0 < OUT;

    int beg = g_rowptr[row], end = g_rowptr[row + 1];
    float a0 = 0.f, a1 = 0.f, b0_ = 0.f, b1_ = 0.f;

    for (int base = beg; base < end; base += 32) {
        int rem = end - base; if (rem > 32) rem = 32;
        int my = (lane < rem) ? g_esrc[base + lane] : 0;
        int j = 0;
        for (; j + 4 <= rem; j += 4) {
            int s0 = __shfl_sync(0xffffffffu, my, j);
            int s1 = __shfl_sync(0xffffffffu, my, j + 1);
            int s2 = __shfl_sync(0xffffffffu, my, j + 2);
            int s3 = __shfl_sync(0xffffffffu, my, j + 3);
            if (valid) {
                float2 v0 = __ldg((const float2*)&Y[(size_t)s0 * OUT + c0]);
                float2 v1 = __ldg((const float2*)&Y[(size_t)s1 * OUT + c0]);
                float2 v2 = __ldg((const float2*)&Y[(size_t)s2 * OUT + c0]);
                float2 v3 = __ldg((const float2*)&Y[(size_t)s3 * OUT + c0]);
                a0 += v0.x; a1 += v0.y;
                b0_ += v1.x; b1_ += v1.y;
                a0 += v2.x; a1 += v2.y;
                b0_ += v3.x; b1_ += v3.y;
            }
        }
        for (; j < rem; j++) {
            int s = __shfl_sync(0xffffffffu, my, j);
            if (valid) {
                float2 v = __ldg((const float2*)&Y[(size_t)s * OUT + c0]);
                a0 += v.x; a1 += v.y;
            }
        }
    }
    a0 += b0_; a1 += b1_;

    float ndv = g_nd[row];
    float v0 = -CUDART_INF_F, v1 = -CUDART_INF_F;
    if (valid) {
        v0 = a0 * ndv + bias[c0];
        v1 = a1 * ndv + bias[c0 + 1];
        if (RELU) { v0 = fmaxf(v0, 0.f); v1 = fmaxf(v1, 0.f); }
    }
    float m = fmaxf(v0, v1);
    #pragma unroll
    for (int o = 16; o; o >>= 1) m = fmaxf(m, __shfl_xor_sync(0xffffffffu, m, o));
    float s = valid ? (__expf(v0 - m) + __expf(v1 - m)) : 0.f;
    #pragma unroll
    for (int o = 16; o; o >>= 1) s += __shfl_xor_sync(0xffffffffu, s, o);
    float ls = logf(s);
    if (valid)
        *(float2*)&Out[(size_t)row * OUT + c0] = make_float2(v0 - m - ls, v1 - m - ls);
}

// ---------------- launcher ----------------------------------------------------
extern "C" void kernel_launch(void* const* d_in, const int* in_sizes, int n_in,
                              void* d_out, int out_size) {
    const float* feats = (const float*)d_in[0];
    const void*  src   = d_in[1];
    const void*  dst   = d_in[2];
    const float* W0    = (const float*)d_in[3];
    const float* b0    = (const float*)d_in[4];
    const float* W1    = (const float*)d_in[5];
    const float* b1    = (const float*)d_in[6];
    const float* W2    = (const float*)d_in[7];
    const float* b2    = (const float*)d_in[8];
    float* out = (float*)d_out;
    int E = in_sizes[1];

    float *p_y = nullptr, *p_h1 = nullptr, *p_h2 = nullptr;
    cudaGetSymbolAddress((void**)&p_y,  g_y);
    cudaGetSymbolAddress((void**)&p_h1, g_h1);
    cudaGetSymbolAddress((void**)&p_h2, g_h2);

    const int GB = (NN + 31) / 32;    // gemm blocks (32 rows each)
    const int SB = (NN + 7) / 8;      // spmm blocks (warp per row)
    const int EB = (E + 255) / 256;   // per-edge blocks
    const int ZB = (NN + 255) / 256;  // zero blocks

    // ---- CSR build with layer-0 GEMM (unscaled) overlapped in one launch
    zero_detect_kernel<<<ZB, 256>>>(src, E);
    histgemm_kernel<<<EB + GB, 256>>>(src, dst, E, EB, feats, W0, p_y);
    scan1_kernel<<<NB, SCAN_BS>>>();
    scan2_kernel<<<1, 32>>>();
    scan3_kernel<<<NB, SCAN_BS>>>(p_y);   // + Y0 *= ns
    place_kernel<<<EB, 256>>>(src, dst, E);

    // ---- layer 0: relu + log_softmax -> g_h1
    spmm_epi_kernel<64, true><<<SB, 256>>>(p_y, b0, p_h1);

    // ---- layer 1: 64 -> 64, relu + log_softmax -> g_h2
    gemm_scale_kernel<64, 64><<<GB, 256>>>(p_h1, W1, p_y);
    spmm_epi_kernel<64, true><<<SB, 256>>>(p_y, b1, p_h2);

    // ---- layer 2: 64 -> 40, log_softmax -> d_out
    gemm_scale_kernel<64, 40><<<GB, 256>>>(p_h2, W2, p_y);
    spmm_epi_kernel<40, false><<<SB, 256>>>(p_y, b2, out);
}